// round 13
// baseline (speedup 1.0000x reference)
#include <cuda_runtime.h>
#include <math.h>

typedef unsigned long long ull;

// ---------------- scratch (__device__ globals; no allocation) ----------------
__device__ float g_x1[128*32*1681];            // conv1 out (relu)      27.5 MB
__device__ float g_upart[2][128*64*289];       // conv2 partial sums  2x 9.5 MB
__device__ float g_x2[2312*8*128];             // squashed u, [r][i][b]  9.5 MB
__device__ float g_scale[1024];                // squash scale per (b,i)
__device__ float g_w1p[3*81*32];               // conv1 w packed [ic][k][oc]
__device__ float g_w2p[32*81*64];              // conv2 w packed [ic*81+k][oc]
__device__ float g_bij[2312*10];               // routing logits
__device__ float g_spart2[68*128*160];         // s split-K partials [sl][b][c*16+o]
__device__ float g_v[128*160];                 // v

// ---------------- f32x2 helpers (FFMA2 only reachable via PTX) ----------------
__device__ __forceinline__ ull pk2(float lo, float hi) {
    ull r; asm("mov.b64 %0, {%1,%2};" : "=l"(r) : "f"(lo), "f"(hi)); return r;
}
__device__ __forceinline__ ull fma2(ull a, ull b, ull c) {
    ull d; asm("fma.rn.f32x2 %0, %1, %2, %3;" : "=l"(d) : "l"(a), "l"(b), "l"(c)); return d;
}
__device__ __forceinline__ void upk2(ull v, float& lo, float& hi) {
    asm("mov.b64 {%0,%1}, %2;" : "=f"(lo), "=f"(hi) : "l"(v));
}

// ---------------- cp.async helpers (LDGSTS: no register staging) ----------------
__device__ __forceinline__ unsigned smem_u32(const void* p) {
    return (unsigned)__cvta_generic_to_shared(p);
}
__device__ __forceinline__ void cpa4(unsigned dst, const float* src) {
    asm volatile("cp.async.ca.shared.global [%0], [%1], 4;" :: "r"(dst), "l"(src) : "memory");
}
__device__ __forceinline__ void cpa16(unsigned dst, const float* src) {
    asm volatile("cp.async.cg.shared.global [%0], [%1], 16;" :: "r"(dst), "l"(src) : "memory");
}
__device__ __forceinline__ void cpa_commit() {
    asm volatile("cp.async.commit_group;" ::: "memory");
}
__device__ __forceinline__ void cpa_wait1() {
    asm volatile("cp.async.wait_group 1;" ::: "memory");
}

// ---------------- init / weight pre-pack ----------------
__global__ void k_init() {
    int i = blockIdx.x*256 + threadIdx.x;
    if (i < 23120) g_bij[i] = 0.f;
}
__global__ void k_pack_w1(const float* __restrict__ conv_w) {
    int idx = blockIdx.x*256 + threadIdx.x;
    if (idx >= 32*3*81) return;
    int oc = idx / 243; int rem = idx % 243;        // rem = ic*81 + k
    g_w1p[rem*32 + oc] = conv_w[idx];
}
__global__ void k_pack_w2(const float* __restrict__ prim_w) {
    int idx = blockIdx.x*256 + threadIdx.x;
    if (idx >= 64*32*81) return;
    int oc = idx / 2592; int rem = idx % 2592;      // rem = ic*81 + k
    g_w2p[rem*64 + oc] = prim_w[idx];
}

// ---------------- conv1: 3->32, 9x9, stride 1, relu. tile 4oc x 4x ----------------
__global__ void __launch_bounds__(256) k_conv1(const float* __restrict__ data,
                                               const float* __restrict__ conv_b) {
    __shared__ __align__(16) float s_in[3*49*52];
    __shared__ __align__(16) float s_w[3*81*4];
    int tid = threadIdx.x;
    int ocg = blockIdx.x;
    int b   = blockIdx.y;
    const float* img = data + b*3*49*49;
    for (int i = tid; i < 3*49*49; i += 256) {
        int ic = i / 2401; int r2 = i % 2401;
        s_in[(ic*49 + r2/49)*52 + (r2%49)] = img[i];
    }
    for (int i = tid; i < 3*49*3; i += 256) {
        int ic = i / 147; int r2 = i % 147;
        s_in[(ic*49 + r2/3)*52 + 49 + (r2%3)] = 0.f;
    }
    for (int i = tid; i < 972; i += 256)
        s_w[i] = g_w1p[(i>>2)*32 + ocg*4 + (i&3)];
    __syncthreads();
    float bs[4];
    #pragma unroll
    for (int j = 0; j < 4; j++) bs[j] = conv_b[ocg*4 + j];
    for (int task = tid; task < 451; task += 256) {
        int oy = task / 11, ox0 = (task % 11) * 4;
        ull acc[2][4];
        #pragma unroll
        for (int p = 0; p < 2; p++)
            #pragma unroll
            for (int s = 0; s < 4; s++) acc[p][s] = pk2(0.f, 0.f);
        for (int ic = 0; ic < 3; ic++) {
            #pragma unroll
            for (int ky = 0; ky < 9; ky++) {
                const float4* rp = (const float4*)&s_in[(ic*49 + oy + ky)*52 + ox0];
                float4 A = rp[0], Bv = rp[1], Cv = rp[2];
                float r[12] = {A.x,A.y,A.z,A.w, Bv.x,Bv.y,Bv.z,Bv.w, Cv.x,Cv.y,Cv.z,Cv.w};
                ull rd[12];
                #pragma unroll
                for (int j = 0; j < 12; j++) rd[j] = pk2(r[j], r[j]);
                const float4* wp = (const float4*)&s_w[(ic*81 + ky*9)*4];
                #pragma unroll
                for (int kx = 0; kx < 9; kx++) {
                    float4 w = wp[kx];
                    ull w0 = pk2(w.x, w.y), w1 = pk2(w.z, w.w);
                    #pragma unroll
                    for (int s = 0; s < 4; s++) {
                        acc[0][s] = fma2(w0, rd[kx+s], acc[0][s]);
                        acc[1][s] = fma2(w1, rd[kx+s], acc[1][s]);
                    }
                }
            }
        }
        float* outb = g_x1 + (b*32 + ocg*4)*1681 + oy*41;
        #pragma unroll
        for (int s = 0; s < 4; s++) {
            int ox = ox0 + s;
            if (ox < 41) {
                float v0,v1,v2,v3;
                upk2(acc[0][s], v0, v1); upk2(acc[1][s], v2, v3);
                outb[0*1681 + ox] = fmaxf(v0 + bs[0], 0.f);
                outb[1*1681 + ox] = fmaxf(v1 + bs[1], 0.f);
                outb[2*1681 + ox] = fmaxf(v2 + bs[2], 0.f);
                outb[3*1681 + ox] = fmaxf(v3 + bs[3], 0.f);
            }
        }
    }
}

// ---------------- conv2 v8: v7 K-split tile + cp.async triple-buffer pipeline -------
// grid (16,128): blockIdx.x = ocg(0..7) + 8*ich(0..1); 16 ics per block.
// Iteration j: cp.async(ic j+1 -> buf (j+1)%3), wait_group 1, ONE barrier, compute buf j%3.
__global__ void __launch_bounds__(96) k_conv2(const float* __restrict__ prim_b) {
    __shared__ __align__(16) float s_in[3][41*44 + 16];   // padded rows + tail pad
    __shared__ __align__(16) float s_w[3][81*8];
    int tid = threadIdx.x;
    int bx  = blockIdx.x;
    int ocg = bx & 7;            // 8 groups of 8 oc
    int ich = bx >> 3;           // ic half: 0 -> ics 0..15, 1 -> ics 16..31
    int b   = blockIdx.y;
    bool active = tid < 85;      // 17 oy x 5 x-quads
    int oy = tid / 5, xq = tid % 5;
    int ibase = oy*2*44 + xq*8;  // 16B-aligned col start
    ull acc[4][4];               // [oc-pair][pos]
    #pragma unroll
    for (int p = 0; p < 4; p++)
        #pragma unroll
        for (int s = 0; s < 4; s++) acc[p][s] = pk2(0.f, 0.f);
    const float* inb = g_x1 + (size_t)b*32*1681 + (size_t)ich*16*1681;
    const float* wband = g_w2p + ocg*8;          // + (icg*81 + k)*64

    // zero pads once in all 3 buffers: cols 41..43 each row + 16-float tail
    #pragma unroll
    for (int bu = 0; bu < 3; bu++) {
        for (int i = tid; i < 123; i += 96) s_in[bu][(i/3)*44 + 41 + (i%3)] = 0.f;
        for (int i = tid; i < 16; i += 96)  s_in[bu][41*44 + i] = 0.f;
    }

    // prologue: stage ic 0 into buffer 0
    {
        const float* plane = inb;
        unsigned di = smem_u32(&s_in[0][0]);
        for (int i = tid; i < 1681; i += 96)
            cpa4(di + ((i/41)*44 + (i%41))*4, plane + i);
        const float* wsl = wband + (size_t)(ich*16)*81*64;
        unsigned dw = smem_u32(&s_w[0][0]);
        for (int k2 = tid; k2 < 162; k2 += 96) {
            int k = k2 >> 1, h = k2 & 1;
            cpa16(dw + k*32 + h*16, wsl + (size_t)k*64 + h*4);
        }
    }
    cpa_commit();

    for (int ic = 0; ic < 16; ic++) {
        if (ic < 15) {
            int nb = (ic + 1) % 3;
            const float* plane = inb + (size_t)(ic+1)*1681;
            unsigned di = smem_u32(&s_in[nb][0]);
            for (int i = tid; i < 1681; i += 96)
                cpa4(di + ((i/41)*44 + (i%41))*4, plane + i);
            const float* wsl = wband + (size_t)(ich*16 + ic + 1)*81*64;
            unsigned dw = smem_u32(&s_w[nb][0]);
            for (int k2 = tid; k2 < 162; k2 += 96) {
                int k = k2 >> 1, h = k2 & 1;
                cpa16(dw + k*32 + h*16, wsl + (size_t)k*64 + h*4);
            }
        }
        cpa_commit();
        cpa_wait1();                 // group for ic is now complete (per thread)
        __syncthreads();             // make all threads' fills visible
        int cb = ic % 3;
        if (active) {
            #pragma unroll
            for (int ky = 0; ky < 9; ky++) {
                const float4* rp = (const float4*)&s_in[cb][ibase + ky*44];
                float4 q0 = rp[0], q1 = rp[1], q2 = rp[2], q3 = rp[3];
                float xv[16] = {q0.x,q0.y,q0.z,q0.w, q1.x,q1.y,q1.z,q1.w,
                                q2.x,q2.y,q2.z,q2.w, q3.x,q3.y,q3.z,q3.w};
                ull rd[15];
                #pragma unroll
                for (int j = 0; j < 15; j++) rd[j] = pk2(xv[j], xv[j]);
                #pragma unroll
                for (int kx = 0; kx < 9; kx++) {
                    const longlong2* wp = (const longlong2*)&s_w[cb][(ky*9 + kx)*8];
                    longlong2 wa = wp[0], wb = wp[1];
                    ull w0 = (ull)wa.x, w1 = (ull)wa.y, w2 = (ull)wb.x, w3 = (ull)wb.y;
                    #pragma unroll
                    for (int s = 0; s < 4; s++) {
                        ull xi = rd[kx + 2*s];
                        acc[0][s] = fma2(w0, xi, acc[0][s]);
                        acc[1][s] = fma2(w1, xi, acc[1][s]);
                        acc[2][s] = fma2(w2, xi, acc[2][s]);
                        acc[3][s] = fma2(w3, xi, acc[3][s]);
                    }
                }
            }
        }
    }
    if (active) {
        float* base = g_upart[ich];
        #pragma unroll
        for (int s = 0; s < 4; s++) {
            int ox = xq*4 + s;
            if (ox < 17) {
                int pos = oy*17 + ox;
                #pragma unroll
                for (int p = 0; p < 4; p++) {
                    float lo, hi; upk2(acc[p][s], lo, hi);
                    int oc0 = ocg*8 + p*2;
                    float b0 = (ich == 0) ? prim_b[oc0]   : 0.f;
                    float b1 = (ich == 0) ? prim_b[oc0+1] : 0.f;
                    base[(size_t)(b*64 + oc0  )*289 + pos] = lo + b0;
                    base[(size_t)(b*64 + oc0+1)*289 + pos] = hi + b1;
                }
            }
        }
    }
}

// ---------------- squash over routes: per (b,i) scale (sums the 2 partials) -------
__global__ void __launch_bounds__(256) k_sqnorm() {
    __shared__ float red[256];
    int bi = blockIdx.x;                     // b*8 + i
    const float* p0 = g_upart[0] + bi*2312;
    const float* p1 = g_upart[1] + bi*2312;
    float s = 0.f;
    for (int k = threadIdx.x; k < 2312; k += 256) { float v = p0[k] + p1[k]; s += v*v; }
    red[threadIdx.x] = s; __syncthreads();
    for (int st = 128; st; st >>= 1) {
        if (threadIdx.x < st) red[threadIdx.x] += red[threadIdx.x + st];
        __syncthreads();
    }
    if (threadIdx.x == 0) {
        float sn = red[0];
        g_scale[bi] = sn / ((1.f + sn) * sqrtf(fmaxf(sn, 1e-30f)));
    }
}

// ---------------- x2 transpose (sums the 2 partials; coalesced both sides) --------
__global__ void __launch_bounds__(256) k_xpose() {
    __shared__ float tile[32][33];
    int ch = blockIdx.x;                 // 0..63
    int st = blockIdx.y;                 // s tile 0..9
    int bt = blockIdx.z;                 // b tile 0..3
    int tx = threadIdx.x & 31, ty = threadIdx.x >> 5;
    int i = ch >> 3, rr = ch & 7;
    int s0 = st*32, b0 = bt*32;
    #pragma unroll
    for (int bb = ty; bb < 32; bb += 8) {
        int s = s0 + tx;
        float v = 0.f;
        if (s < 289) {
            int b = b0 + bb;
            size_t idx = (size_t)(b*64 + ch)*289 + s;
            v = g_scale[b*8 + i] * (g_upart[0][idx] + g_upart[1][idx]);
        }
        tile[bb][tx] = v;
    }
    __syncthreads();
    #pragma unroll
    for (int ss = ty; ss < 32; ss += 8) {
        int s = s0 + ss;
        if (s < 289) {
            int r = rr*289 + s;
            g_x2[(size_t)r*1024 + i*128 + b0 + tx] = tile[tx][ss];
        }
    }
}

// ---------------- routing (u_hat never materialized; softmax fused) -------------
__global__ void __launch_bounds__(128) k_spass2(const float* __restrict__ W_digit) {
    __shared__ float s_c[34];
    __shared__ __align__(16) float s_w[34*128];     // [rl][i*16+o], c-scaled
    int sl = blockIdx.x, c = blockIdx.y, t = threadIdx.x;
    int r0 = sl*34;
    if (t < 34) {                                    // inline softmax of b_ij row
        const float* bp = g_bij + (r0 + t)*10;
        float v[10], m = -1e30f;
        #pragma unroll
        for (int j = 0; j < 10; j++) { v[j] = bp[j]; m = fmaxf(m, v[j]); }
        float s = 0.f;
        #pragma unroll
        for (int j = 0; j < 10; j++) s += expf(v[j] - m);
        s_c[t] = expf(v[c] - m) / s;
    }
    __syncthreads();
    for (int e = t; e < 34*128; e += 128) {
        int rl = e >> 7, rem = e & 127;             // rem = o*8+i
        int o = rem >> 3, i = rem & 7;
        s_w[rl*128 + i*16 + o] = s_c[rl] * W_digit[(size_t)(r0+rl)*1280 + c*128 + rem];
    }
    __syncthreads();
    ull acc[8];
    #pragma unroll
    for (int p = 0; p < 8; p++) acc[p] = pk2(0.f, 0.f);
    int b = t;
    for (int rl = 0; rl < 34; rl++) {
        int r = r0 + rl;
        float xv[8];
        #pragma unroll
        for (int i = 0; i < 8; i++) xv[i] = g_x2[(r*8+i)*128 + b];
        const ull* wrow = (const ull*)&s_w[rl*128];
        #pragma unroll
        for (int i = 0; i < 8; i++) {
            ull xi = pk2(xv[i], xv[i]);
            #pragma unroll
            for (int op = 0; op < 8; op++)
                acc[op] = fma2(wrow[i*8+op], xi, acc[op]);
        }
    }
    float* outp = g_spart2 + ((size_t)(sl*128 + b))*160 + c*16;
    #pragma unroll
    for (int op = 0; op < 8; op++) {
        float lo, hi; upk2(acc[op], lo, hi);
        outp[op*2] = lo; outp[op*2+1] = hi;
    }
}

// reduce 68 slices + squash over o (reads coalesced: [sl][b][t])
__global__ void __launch_bounds__(160) k_reduce2(float* __restrict__ out, int write_out) {
    int b = blockIdx.x, t = threadIdx.x;            // t = c*16+o
    float s = 0.f;
    #pragma unroll 4
    for (int sl = 0; sl < 68; sl++)
        s += g_spart2[((size_t)(sl*128 + b))*160 + t];
    float sq = s*s;
    #pragma unroll
    for (int off = 8; off; off >>= 1) sq += __shfl_xor_sync(0xffffffffu, sq, off, 16);
    float scale = sq / ((1.f + sq) * sqrtf(fmaxf(sq, 1e-30f)));
    float v = s * scale;
    g_v[b*160 + t] = v;
    if (write_out) out[b*160 + t] = v;
}

// a[r,c] = (1/128) sum_{o,i} W[r,c,o,i] * (sum_b x2[r,i,b] v[b,c,o]); b_ij += a
__global__ void __launch_bounds__(160) k_apass2(const float* __restrict__ W_digit) {
    extern __shared__ float sm[];
    float* s_v = sm;             // 20480 floats (80 KB)
    float* s_x = sm + 20480;     // 8192 floats  (32 KB), layout [rr][b][i]
    int t = threadIdx.x;
    int r0 = blockIdx.x * 8;
    for (int idx = t; idx < 20480; idx += 160) s_v[idx] = g_v[idx];
    for (int d = t; d < 8192; d += 160) {
        int rr = d >> 10, rem = d & 1023, b = rem >> 3, i = rem & 7;
        s_x[d] = g_x2[(size_t)(r0+rr)*1024 + i*128 + b];
    }
    __syncthreads();
    for (int rr = 0; rr < 8; rr++) {
        int r = r0 + rr;
        ull accp[4];
        #pragma unroll
        for (int p = 0; p < 4; p++) accp[p] = pk2(0.f, 0.f);
        #pragma unroll 4
        for (int b = 0; b < 128; b++) {
            float vb = s_v[b*160 + t];
            ull vv = pk2(vb, vb);
            const ull* xp = (const ull*)&s_x[rr*1024 + b*8];
            #pragma unroll
            for (int ip = 0; ip < 4; ip++)
                accp[ip] = fma2(xp[ip], vv, accp[ip]);
        }
        float G[8];
        #pragma unroll
        for (int ip = 0; ip < 4; ip++) upk2(accp[ip], G[2*ip], G[2*ip+1]);
        const float4* wp = (const float4*)(W_digit + (size_t)r*1280 + t*8);
        float4 wa = wp[0], wb4 = wp[1];
        float partial = wa.x*G[0] + wa.y*G[1] + wa.z*G[2] + wa.w*G[3]
                      + wb4.x*G[4] + wb4.y*G[5] + wb4.z*G[6] + wb4.w*G[7];
        #pragma unroll
        for (int off = 8; off; off >>= 1) partial += __shfl_xor_sync(0xffffffffu, partial, off, 16);
        if ((t & 15) == 0) g_bij[r*10 + (t >> 4)] += partial * (1.f/128.f);
    }
}

// ---------------- head MLP + sigmoid ----------------
__global__ void __launch_bounds__(128) k_head(const float* __restrict__ w1, const float* __restrict__ b1,
                                              const float* __restrict__ w2, const float* __restrict__ b2,
                                              float* __restrict__ out) {
    __shared__ float s_v[160];
    __shared__ float s_red[128];
    int b = blockIdx.x, t = threadIdx.x;
    for (int i = t; i < 160; i += 128) s_v[i] = g_v[b*160 + i];
    __syncthreads();
    for (int c = 0; c < 10; c++) {
        float hv = 0.f;
        if (t < 100) {
            float a = b1[c*100 + t];
            #pragma unroll
            for (int i = 0; i < 16; i++) a += s_v[c*16 + i] * w1[(c*16 + i)*100 + t];
            hv = tanhf(a) * w2[c*100 + t];
        }
        s_red[t] = hv;
        __syncthreads();
        for (int st = 64; st; st >>= 1) {
            if (t < st) s_red[t] += s_red[t + st];
            __syncthreads();
        }
        if (t == 0) {
            float logit = s_red[0] + b2[c];
            out[20480 + c*128 + b] = 1.f / (1.f + expf(-logit));
        }
        __syncthreads();
    }
}

// ---------------- launch (conv2 at 0-based index 3: the profiled slot) ----------------
extern "C" void kernel_launch(void* const* d_in, const int* in_sizes, int n_in,
                              void* d_out, int out_size) {
    const float* data    = (const float*)d_in[0];
    const float* conv_w  = (const float*)d_in[1];
    const float* conv_b  = (const float*)d_in[2];
    const float* prim_w  = (const float*)d_in[3];
    const float* prim_b  = (const float*)d_in[4];
    const float* W_digit = (const float*)d_in[5];
    const float* head_w1 = (const float*)d_in[6];
    const float* head_b1 = (const float*)d_in[7];
    const float* head_w2 = (const float*)d_in[8];
    const float* head_b2 = (const float*)d_in[9];
    float* out = (float*)d_out;

    cudaFuncSetAttribute(k_apass2, cudaFuncAttributeMaxDynamicSharedMemorySize, 114688);

    k_pack_w1<<<(7776 + 255)/256, 256>>>(conv_w);        // 0
    k_pack_w2<<<(165888 + 255)/256, 256>>>(prim_w);      // 1
    k_conv1<<<dim3(8, 128), 256>>>(data, conv_b);        // 2
    k_conv2<<<dim3(16, 128), 96>>>(prim_b);              // 3  <- profiled slot
    k_init<<<91, 256>>>();                                // 4
    k_sqnorm<<<1024, 256>>>();                            // 5
    k_xpose<<<dim3(64, 10, 4), 256>>>();                  // 6
    for (int it = 0; it < 3; it++) {
        k_spass2<<<dim3(68, 10), 128>>>(W_digit);
        k_reduce2<<<128, 160>>>(out, it == 2 ? 1 : 0);
        if (it < 2) k_apass2<<<289, 160, 114688>>>(W_digit);
    }
    k_head<<<128, 128>>>(head_w1, head_b1, head_w2, head_b2, out);
}

// round 14
// speedup vs baseline: 1.0958x; 1.0958x over previous
#include <cuda_runtime.h>
#include <math.h>

typedef unsigned long long ull;

// ---------------- scratch (__device__ globals; no allocation) ----------------
__device__ float g_x1[128*32*1681];            // conv1 out (relu)      27.5 MB
__device__ float g_upart[2][128*64*289];       // conv2 partial sums  2x 9.5 MB
__device__ float g_x2[2312*8*128];             // squashed u, [r][i][b]  9.5 MB
__device__ float g_scale[1024];                // squash scale per (b,i)
__device__ float g_w1p[3*81*32];               // conv1 w packed [ic][k][oc]
__device__ float g_w2p[32*81*64];              // conv2 w packed [ic*81+k][oc]
__device__ float g_bij[2312*10];               // routing logits
__device__ float g_spart2[68*128*160];         // s split-K partials [sl][b][c*16+o]
__device__ float g_v[128*160];                 // v

// ---------------- f32x2 helpers (FFMA2 only reachable via PTX) ----------------
__device__ __forceinline__ ull pk2(float lo, float hi) {
    ull r; asm("mov.b64 %0, {%1,%2};" : "=l"(r) : "f"(lo), "f"(hi)); return r;
}
__device__ __forceinline__ ull fma2(ull a, ull b, ull c) {
    ull d; asm("fma.rn.f32x2 %0, %1, %2, %3;" : "=l"(d) : "l"(a), "l"(b), "l"(c)); return d;
}
__device__ __forceinline__ void upk2(ull v, float& lo, float& hi) {
    asm("mov.b64 {%0,%1}, %2;" : "=f"(lo), "=f"(hi) : "l"(v));
}

// ---------------- prep: zero b_ij + pack conv1 weights (fused) ----------------
__global__ void k_prep(const float* __restrict__ conv_w) {
    int idx = blockIdx.x*256 + threadIdx.x;
    if (idx < 23120) g_bij[idx] = 0.f;
    if (idx < 32*3*81) {
        int oc = idx / 243; int rem = idx % 243;    // rem = ic*81 + k
        g_w1p[rem*32 + oc] = conv_w[idx];
    }
}
__global__ void k_pack_w2(const float* __restrict__ prim_w) {
    int idx = blockIdx.x*256 + threadIdx.x;
    if (idx >= 64*32*81) return;
    int oc = idx / 2592; int rem = idx % 2592;      // rem = ic*81 + k
    g_w2p[rem*64 + oc] = prim_w[idx];
}

// ---------------- conv1: 3->32, 9x9, stride 1, relu. tile 4oc x 4x ----------------
__global__ void __launch_bounds__(256) k_conv1(const float* __restrict__ data,
                                               const float* __restrict__ conv_b) {
    __shared__ __align__(16) float s_in[3*49*52];
    __shared__ __align__(16) float s_w[3*81*4];
    int tid = threadIdx.x;
    int ocg = blockIdx.x;
    int b   = blockIdx.y;
    const float* img = data + b*3*49*49;
    for (int i = tid; i < 3*49*49; i += 256) {
        int ic = i / 2401; int r2 = i % 2401;
        s_in[(ic*49 + r2/49)*52 + (r2%49)] = img[i];
    }
    for (int i = tid; i < 3*49*3; i += 256) {
        int ic = i / 147; int r2 = i % 147;
        s_in[(ic*49 + r2/3)*52 + 49 + (r2%3)] = 0.f;
    }
    for (int i = tid; i < 972; i += 256)
        s_w[i] = g_w1p[(i>>2)*32 + ocg*4 + (i&3)];
    __syncthreads();
    float bs[4];
    #pragma unroll
    for (int j = 0; j < 4; j++) bs[j] = conv_b[ocg*4 + j];
    for (int task = tid; task < 451; task += 256) {
        int oy = task / 11, ox0 = (task % 11) * 4;
        ull acc[2][4];
        #pragma unroll
        for (int p = 0; p < 2; p++)
            #pragma unroll
            for (int s = 0; s < 4; s++) acc[p][s] = pk2(0.f, 0.f);
        for (int ic = 0; ic < 3; ic++) {
            #pragma unroll
            for (int ky = 0; ky < 9; ky++) {
                const float4* rp = (const float4*)&s_in[(ic*49 + oy + ky)*52 + ox0];
                float4 A = rp[0], Bv = rp[1], Cv = rp[2];
                float r[12] = {A.x,A.y,A.z,A.w, Bv.x,Bv.y,Bv.z,Bv.w, Cv.x,Cv.y,Cv.z,Cv.w};
                ull rd[12];
                #pragma unroll
                for (int j = 0; j < 12; j++) rd[j] = pk2(r[j], r[j]);
                const float4* wp = (const float4*)&s_w[(ic*81 + ky*9)*4];
                #pragma unroll
                for (int kx = 0; kx < 9; kx++) {
                    float4 w = wp[kx];
                    ull w0 = pk2(w.x, w.y), w1 = pk2(w.z, w.w);
                    #pragma unroll
                    for (int s = 0; s < 4; s++) {
                        acc[0][s] = fma2(w0, rd[kx+s], acc[0][s]);
                        acc[1][s] = fma2(w1, rd[kx+s], acc[1][s]);
                    }
                }
            }
        }
        float* outb = g_x1 + (b*32 + ocg*4)*1681 + oy*41;
        #pragma unroll
        for (int s = 0; s < 4; s++) {
            int ox = ox0 + s;
            if (ox < 41) {
                float v0,v1,v2,v3;
                upk2(acc[0][s], v0, v1); upk2(acc[1][s], v2, v3);
                outb[0*1681 + ox] = fmaxf(v0 + bs[0], 0.f);
                outb[1*1681 + ox] = fmaxf(v1 + bs[1], 0.f);
                outb[2*1681 + ox] = fmaxf(v2 + bs[2], 0.f);
                outb[3*1681 + ox] = fmaxf(v3 + bs[3], 0.f);
            }
        }
    }
}

// ---------------- conv2 v9: 16 oc x 2 pos per thread, 2-way K-split ----------------
// Slot mix per (ky,kx): 4 weight LDS.128 feed 16 FMA2 -> ~70% of issue slots are FMA2.
// grid (8,128): blockIdx.x = ocg(0..3) + 4*ich(0..1); 16 ics per block; 160 thr.
__global__ void __launch_bounds__(160) k_conv2(const float* __restrict__ prim_b) {
    __shared__ __align__(16) float s_in[41*44];
    __shared__ __align__(16) float s_w[81*16];
    int tid = threadIdx.x;
    int bx  = blockIdx.x;
    int ocg = bx & 3;            // 4 groups of 16 oc
    int ich = bx >> 2;           // ic half
    int b   = blockIdx.y;
    int oy = tid / 9, oxp = tid % 9, ix0 = 4*oxp;
    bool active = tid < 153;
    ull acc[8][2];               // [oc-pair][pos]
    #pragma unroll
    for (int p = 0; p < 8; p++)
        #pragma unroll
        for (int s = 0; s < 2; s++) acc[p][s] = pk2(0.f, 0.f);
    const float* inb = g_x1 + (size_t)b*32*1681 + (size_t)ich*16*1681;

    // zero pad cols 41..43 once (fills never touch them)
    for (int i = tid; i < 123; i += 160) s_in[(i/3)*44 + 41 + (i%3)] = 0.f;

    for (int ic = 0; ic < 16; ic++) {
        __syncthreads();
        for (int i = tid; i < 1681; i += 160)
            s_in[(i/41)*44 + (i%41)] = inb[(size_t)ic*1681 + i];
        int icg = ich*16 + ic;
        for (int i = tid; i < 1296; i += 160)
            s_w[i] = g_w2p[(icg*81 + (i>>4))*64 + ocg*16 + (i&15)];
        __syncthreads();
        if (active) {
            #pragma unroll
            for (int ky = 0; ky < 9; ky++) {
                const float4* rp = (const float4*)&s_in[(oy*2 + ky)*44 + ix0];
                float4 A = rp[0], Bv = rp[1], Cv = rp[2];
                float r[12] = {A.x,A.y,A.z,A.w, Bv.x,Bv.y,Bv.z,Bv.w, Cv.x,Cv.y,Cv.z,Cv.w};
                ull rd[11];
                #pragma unroll
                for (int j = 0; j < 11; j++) rd[j] = pk2(r[j], r[j]);
                #pragma unroll
                for (int kx = 0; kx < 9; kx++) {
                    const ull* w = (const ull*)&s_w[(ky*9 + kx)*16];
                    ull i0 = rd[kx], i1 = rd[kx+2];
                    #pragma unroll
                    for (int p = 0; p < 8; p++) {
                        ull wv = w[p];
                        acc[p][0] = fma2(wv, i0, acc[p][0]);
                        acc[p][1] = fma2(wv, i1, acc[p][1]);
                    }
                }
            }
        }
    }
    if (active) {
        float* base = g_upart[ich];
        int ox0 = 2*oxp;
        #pragma unroll
        for (int s = 0; s < 2; s++) {
            int ox = ox0 + s;
            if (ox < 17) {
                int pos = oy*17 + ox;
                #pragma unroll
                for (int p = 0; p < 8; p++) {
                    float lo, hi; upk2(acc[p][s], lo, hi);
                    int oc0 = ocg*16 + p*2;
                    float b0 = (ich == 0) ? prim_b[oc0]   : 0.f;
                    float b1 = (ich == 0) ? prim_b[oc0+1] : 0.f;
                    base[(size_t)(b*64 + oc0  )*289 + pos] = lo + b0;
                    base[(size_t)(b*64 + oc0+1)*289 + pos] = hi + b1;
                }
            }
        }
    }
}

// ---------------- squash over routes: per (b,i) scale (sums the 2 partials) -------
__global__ void __launch_bounds__(256) k_sqnorm() {
    __shared__ float red[256];
    int bi = blockIdx.x;                     // b*8 + i
    const float* p0 = g_upart[0] + bi*2312;
    const float* p1 = g_upart[1] + bi*2312;
    float s = 0.f;
    for (int k = threadIdx.x; k < 2312; k += 256) { float v = p0[k] + p1[k]; s += v*v; }
    red[threadIdx.x] = s; __syncthreads();
    for (int st = 128; st; st >>= 1) {
        if (threadIdx.x < st) red[threadIdx.x] += red[threadIdx.x + st];
        __syncthreads();
    }
    if (threadIdx.x == 0) {
        float sn = red[0];
        g_scale[bi] = sn / ((1.f + sn) * sqrtf(fmaxf(sn, 1e-30f)));
    }
}

// ---------------- x2 transpose (sums the 2 partials; coalesced both sides) --------
__global__ void __launch_bounds__(256) k_xpose() {
    __shared__ float tile[32][33];
    int ch = blockIdx.x;                 // 0..63
    int st = blockIdx.y;                 // s tile 0..9
    int bt = blockIdx.z;                 // b tile 0..3
    int tx = threadIdx.x & 31, ty = threadIdx.x >> 5;
    int i = ch >> 3, rr = ch & 7;
    int s0 = st*32, b0 = bt*32;
    #pragma unroll
    for (int bb = ty; bb < 32; bb += 8) {
        int s = s0 + tx;
        float v = 0.f;
        if (s < 289) {
            int b = b0 + bb;
            size_t idx = (size_t)(b*64 + ch)*289 + s;
            v = g_scale[b*8 + i] * (g_upart[0][idx] + g_upart[1][idx]);
        }
        tile[bb][tx] = v;
    }
    __syncthreads();
    #pragma unroll
    for (int ss = ty; ss < 32; ss += 8) {
        int s = s0 + ss;
        if (s < 289) {
            int r = rr*289 + s;
            g_x2[(size_t)r*1024 + i*128 + b0 + tx] = tile[tx][ss];
        }
    }
}

// ---------------- routing (u_hat never materialized; softmax fused) -------------
__global__ void __launch_bounds__(128) k_spass2(const float* __restrict__ W_digit) {
    __shared__ float s_c[34];
    __shared__ __align__(16) float s_w[34*128];     // [rl][i*16+o], c-scaled
    int sl = blockIdx.x, c = blockIdx.y, t = threadIdx.x;
    int r0 = sl*34;
    if (t < 34) {                                    // inline softmax of b_ij row
        const float* bp = g_bij + (r0 + t)*10;
        float v[10], m = -1e30f;
        #pragma unroll
        for (int j = 0; j < 10; j++) { v[j] = bp[j]; m = fmaxf(m, v[j]); }
        float s = 0.f;
        #pragma unroll
        for (int j = 0; j < 10; j++) s += expf(v[j] - m);
        s_c[t] = expf(v[c] - m) / s;
    }
    __syncthreads();
    for (int e = t; e < 34*128; e += 128) {
        int rl = e >> 7, rem = e & 127;             // rem = o*8+i
        int o = rem >> 3, i = rem & 7;
        s_w[rl*128 + i*16 + o] = s_c[rl] * W_digit[(size_t)(r0+rl)*1280 + c*128 + rem];
    }
    __syncthreads();
    ull acc[8];
    #pragma unroll
    for (int p = 0; p < 8; p++) acc[p] = pk2(0.f, 0.f);
    int b = t;
    for (int rl = 0; rl < 34; rl++) {
        int r = r0 + rl;
        float xv[8];
        #pragma unroll
        for (int i = 0; i < 8; i++) xv[i] = g_x2[(r*8+i)*128 + b];
        const ull* wrow = (const ull*)&s_w[rl*128];
        #pragma unroll
        for (int i = 0; i < 8; i++) {
            ull xi = pk2(xv[i], xv[i]);
            #pragma unroll
            for (int op = 0; op < 8; op++)
                acc[op] = fma2(wrow[i*8+op], xi, acc[op]);
        }
    }
    float* outp = g_spart2 + ((size_t)(sl*128 + b))*160 + c*16;
    #pragma unroll
    for (int op = 0; op < 8; op++) {
        float lo, hi; upk2(acc[op], lo, hi);
        outp[op*2] = lo; outp[op*2+1] = hi;
    }
}

// reduce 68 slices + squash over o; on the final iteration also runs the head MLP
__global__ void __launch_bounds__(160) k_reduce2(float* __restrict__ out, int write_out,
                                                 const float* __restrict__ w1,
                                                 const float* __restrict__ b1,
                                                 const float* __restrict__ w2,
                                                 const float* __restrict__ b2) {
    __shared__ float s_v[160];
    __shared__ float s_red[128];
    int b = blockIdx.x, t = threadIdx.x;            // t = c*16+o
    float s = 0.f;
    #pragma unroll 4
    for (int sl = 0; sl < 68; sl++)
        s += g_spart2[((size_t)(sl*128 + b))*160 + t];
    float sq = s*s;
    #pragma unroll
    for (int off = 8; off; off >>= 1) sq += __shfl_xor_sync(0xffffffffu, sq, off, 16);
    float scale = sq / ((1.f + sq) * sqrtf(fmaxf(sq, 1e-30f)));
    float v = s * scale;
    g_v[b*160 + t] = v;
    if (!write_out) return;
    // ---- final iteration: emit v and run head MLP for this b ----
    out[b*160 + t] = v;
    s_v[t] = v;
    __syncthreads();
    for (int c = 0; c < 10; c++) {
        float hv = 0.f;
        if (t < 100) {
            float a = b1[c*100 + t];
            #pragma unroll
            for (int i = 0; i < 16; i++) a += s_v[c*16 + i] * w1[(c*16 + i)*100 + t];
            hv = tanhf(a) * w2[c*100 + t];
        }
        if (t < 128) s_red[t] = hv;
        __syncthreads();
        for (int st = 64; st; st >>= 1) {
            if (t < st) s_red[t] += s_red[t + st];
            __syncthreads();
        }
        if (t == 0) {
            float logit = s_red[0] + b2[c];
            out[20480 + c*128 + b] = 1.f / (1.f + expf(-logit));
        }
        __syncthreads();
    }
}

// a[r,c] = (1/128) sum_{o,i} W[r,c,o,i] * (sum_b x2[r,i,b] v[b,c,o]); b_ij += a
__global__ void __launch_bounds__(160) k_apass2(const float* __restrict__ W_digit) {
    extern __shared__ float sm[];
    float* s_v = sm;             // 20480 floats (80 KB)
    float* s_x = sm + 20480;     // 8192 floats  (32 KB), layout [rr][b][i]
    int t = threadIdx.x;
    int r0 = blockIdx.x * 8;
    for (int idx = t; idx < 20480; idx += 160) s_v[idx] = g_v[idx];
    for (int d = t; d < 8192; d += 160) {
        int rr = d >> 10, rem = d & 1023, b = rem >> 3, i = rem & 7;
        s_x[d] = g_x2[(size_t)(r0+rr)*1024 + i*128 + b];
    }
    __syncthreads();
    for (int rr = 0; rr < 8; rr++) {
        int r = r0 + rr;
        ull accp[4];
        #pragma unroll
        for (int p = 0; p < 4; p++) accp[p] = pk2(0.f, 0.f);
        #pragma unroll 4
        for (int b = 0; b < 128; b++) {
            float vb = s_v[b*160 + t];
            ull vv = pk2(vb, vb);
            const ull* xp = (const ull*)&s_x[rr*1024 + b*8];
            #pragma unroll
            for (int ip = 0; ip < 4; ip++)
                accp[ip] = fma2(xp[ip], vv, accp[ip]);
        }
        float G[8];
        #pragma unroll
        for (int ip = 0; ip < 4; ip++) upk2(accp[ip], G[2*ip], G[2*ip+1]);
        const float4* wp = (const float4*)(W_digit + (size_t)r*1280 + t*8);
        float4 wa = wp[0], wb4 = wp[1];
        float partial = wa.x*G[0] + wa.y*G[1] + wa.z*G[2] + wa.w*G[3]
                      + wb4.x*G[4] + wb4.y*G[5] + wb4.z*G[6] + wb4.w*G[7];
        #pragma unroll
        for (int off = 8; off; off >>= 1) partial += __shfl_xor_sync(0xffffffffu, partial, off, 16);
        if ((t & 15) == 0) g_bij[r*10 + (t >> 4)] += partial * (1.f/128.f);
    }
}

// ---------------- launch (conv2 at 0-based index 3: the profiled slot) ----------------
extern "C" void kernel_launch(void* const* d_in, const int* in_sizes, int n_in,
                              void* d_out, int out_size) {
    const float* data    = (const float*)d_in[0];
    const float* conv_w  = (const float*)d_in[1];
    const float* conv_b  = (const float*)d_in[2];
    const float* prim_w  = (const float*)d_in[3];
    const float* prim_b  = (const float*)d_in[4];
    const float* W_digit = (const float*)d_in[5];
    const float* head_w1 = (const float*)d_in[6];
    const float* head_b1 = (const float*)d_in[7];
    const float* head_w2 = (const float*)d_in[8];
    const float* head_b2 = (const float*)d_in[9];
    float* out = (float*)d_out;

    cudaFuncSetAttribute(k_apass2, cudaFuncAttributeMaxDynamicSharedMemorySize, 114688);

    k_prep<<<91, 256>>>(conv_w);                          // 0 (init + pack_w1)
    k_pack_w2<<<(165888 + 255)/256, 256>>>(prim_w);       // 1
    k_conv1<<<dim3(8, 128), 256>>>(data, conv_b);         // 2
    k_conv2<<<dim3(8, 128), 160>>>(prim_b);               // 3  <- profiled slot
    k_sqnorm<<<1024, 256>>>();                             // 4
    k_xpose<<<dim3(64, 10, 4), 256>>>();                   // 5
    for (int it = 0; it < 3; it++) {
        k_spass2<<<dim3(68, 10), 128>>>(W_digit);
        k_reduce2<<<128, 160>>>(out, it == 2 ? 1 : 0,
                                head_w1, head_b1, head_w2, head_b2);
        if (it < 2) k_apass2<<<289, 160, 114688>>>(W_digit);
    }
}

// round 15
// speedup vs baseline: 1.1229x; 1.0247x over previous
#include <cuda_runtime.h>
#include <math.h>

typedef unsigned long long ull;

// ---------------- scratch (__device__ globals; no allocation) ----------------
__device__ float g_x1[128*32*1681];            // conv1 out (relu)      27.5 MB
__device__ float g_upart[4][128*64*289];       // conv2 partial sums  4x 9.5 MB
__device__ float g_x2[2312*8*128];             // squashed u, [r][i][b]  9.5 MB
__device__ float g_scale[1024];                // squash scale per (b,i)
__device__ float g_w1p[3*81*32];               // conv1 w packed [ic][k][oc]
__device__ float g_w2p[32*81*64];              // conv2 w packed [ic*81+k][oc]
__device__ float g_bij[2312*10];               // routing logits
__device__ float g_spart2[68*128*160];         // s split-K partials [sl][b][c*16+o]
__device__ float g_v[128*160];                 // v

// ---------------- f32x2 helpers (FFMA2 only reachable via PTX) ----------------
__device__ __forceinline__ ull pk2(float lo, float hi) {
    ull r; asm("mov.b64 %0, {%1,%2};" : "=l"(r) : "f"(lo), "f"(hi)); return r;
}
__device__ __forceinline__ ull fma2(ull a, ull b, ull c) {
    ull d; asm("fma.rn.f32x2 %0, %1, %2, %3;" : "=l"(d) : "l"(a), "l"(b), "l"(c)); return d;
}
__device__ __forceinline__ void upk2(ull v, float& lo, float& hi) {
    asm("mov.b64 {%0,%1}, %2;" : "=f"(lo), "=f"(hi) : "l"(v));
}

// ---------------- prep: zero b_ij + pack conv1 weights (fused) ----------------
__global__ void k_prep(const float* __restrict__ conv_w) {
    int idx = blockIdx.x*256 + threadIdx.x;
    if (idx < 23120) g_bij[idx] = 0.f;
    if (idx < 32*3*81) {
        int oc = idx / 243; int rem = idx % 243;    // rem = ic*81 + k
        g_w1p[rem*32 + oc] = conv_w[idx];
    }
}
__global__ void k_pack_w2(const float* __restrict__ prim_w) {
    int idx = blockIdx.x*256 + threadIdx.x;
    if (idx >= 64*32*81) return;
    int oc = idx / 2592; int rem = idx % 2592;      // rem = ic*81 + k
    g_w2p[rem*64 + oc] = prim_w[idx];
}

// ---------------- conv1: 3->32, 9x9, stride 1, relu. tile 4oc x 4x ----------------
__global__ void __launch_bounds__(256) k_conv1(const float* __restrict__ data,
                                               const float* __restrict__ conv_b) {
    __shared__ __align__(16) float s_in[3*49*52];
    __shared__ __align__(16) float s_w[3*81*4];
    int tid = threadIdx.x;
    int ocg = blockIdx.x;
    int b   = blockIdx.y;
    const float* img = data + b*3*49*49;
    for (int i = tid; i < 3*49*49; i += 256) {
        int ic = i / 2401; int r2 = i % 2401;
        s_in[(ic*49 + r2/49)*52 + (r2%49)] = img[i];
    }
    for (int i = tid; i < 3*49*3; i += 256) {
        int ic = i / 147; int r2 = i % 147;
        s_in[(ic*49 + r2/3)*52 + 49 + (r2%3)] = 0.f;
    }
    for (int i = tid; i < 972; i += 256)
        s_w[i] = g_w1p[(i>>2)*32 + ocg*4 + (i&3)];
    __syncthreads();
    float bs[4];
    #pragma unroll
    for (int j = 0; j < 4; j++) bs[j] = conv_b[ocg*4 + j];
    for (int task = tid; task < 451; task += 256) {
        int oy = task / 11, ox0 = (task % 11) * 4;
        ull acc[2][4];
        #pragma unroll
        for (int p = 0; p < 2; p++)
            #pragma unroll
            for (int s = 0; s < 4; s++) acc[p][s] = pk2(0.f, 0.f);
        for (int ic = 0; ic < 3; ic++) {
            #pragma unroll
            for (int ky = 0; ky < 9; ky++) {
                const float4* rp = (const float4*)&s_in[(ic*49 + oy + ky)*52 + ox0];
                float4 A = rp[0], Bv = rp[1], Cv = rp[2];
                float r[12] = {A.x,A.y,A.z,A.w, Bv.x,Bv.y,Bv.z,Bv.w, Cv.x,Cv.y,Cv.z,Cv.w};
                ull rd[12];
                #pragma unroll
                for (int j = 0; j < 12; j++) rd[j] = pk2(r[j], r[j]);
                const float4* wp = (const float4*)&s_w[(ic*81 + ky*9)*4];
                #pragma unroll
                for (int kx = 0; kx < 9; kx++) {
                    float4 w = wp[kx];
                    ull w0 = pk2(w.x, w.y), w1 = pk2(w.z, w.w);
                    #pragma unroll
                    for (int s = 0; s < 4; s++) {
                        acc[0][s] = fma2(w0, rd[kx+s], acc[0][s]);
                        acc[1][s] = fma2(w1, rd[kx+s], acc[1][s]);
                    }
                }
            }
        }
        float* outb = g_x1 + (b*32 + ocg*4)*1681 + oy*41;
        #pragma unroll
        for (int s = 0; s < 4; s++) {
            int ox = ox0 + s;
            if (ox < 41) {
                float v0,v1,v2,v3;
                upk2(acc[0][s], v0, v1); upk2(acc[1][s], v2, v3);
                outb[0*1681 + ox] = fmaxf(v0 + bs[0], 0.f);
                outb[1*1681 + ox] = fmaxf(v1 + bs[1], 0.f);
                outb[2*1681 + ox] = fmaxf(v2 + bs[2], 0.f);
                outb[3*1681 + ox] = fmaxf(v3 + bs[3], 0.f);
            }
        }
    }
}

// ---------------- conv2 v10: 16 oc x 2 pos per thread, 4-way K-split, LDS.128 w ----
// grid (16,128): blockIdx.x = ocg(0..3) + 4*ich(0..3); 8 ics per block; 160 thr.
__global__ void __launch_bounds__(160) k_conv2(const float* __restrict__ prim_b) {
    __shared__ __align__(16) float s_in[41*44];
    __shared__ __align__(16) float s_w[81*16];
    int tid = threadIdx.x;
    int bx  = blockIdx.x;
    int ocg = bx & 3;            // 4 groups of 16 oc
    int ich = bx >> 2;           // ic quarter (0..3)
    int b   = blockIdx.y;
    int oy = tid / 9, oxp = tid % 9, ix0 = 4*oxp;
    bool active = tid < 153;
    ull acc[8][2];               // [oc-pair][pos]
    #pragma unroll
    for (int p = 0; p < 8; p++)
        #pragma unroll
        for (int s = 0; s < 2; s++) acc[p][s] = pk2(0.f, 0.f);
    const float* inb = g_x1 + (size_t)b*32*1681 + (size_t)ich*8*1681;

    // zero pad cols 41..43 once (fills never touch them)
    for (int i = tid; i < 123; i += 160) s_in[(i/3)*44 + 41 + (i%3)] = 0.f;

    for (int ic = 0; ic < 8; ic++) {
        __syncthreads();
        for (int i = tid; i < 1681; i += 160)
            s_in[(i/41)*44 + (i%41)] = inb[(size_t)ic*1681 + i];
        int icg = ich*8 + ic;
        for (int i = tid; i < 1296; i += 160)
            s_w[i] = g_w2p[(icg*81 + (i>>4))*64 + ocg*16 + (i&15)];
        __syncthreads();
        if (active) {
            #pragma unroll
            for (int ky = 0; ky < 9; ky++) {
                const float4* rp = (const float4*)&s_in[(oy*2 + ky)*44 + ix0];
                float4 A = rp[0], Bv = rp[1], Cv = rp[2];
                float r[12] = {A.x,A.y,A.z,A.w, Bv.x,Bv.y,Bv.z,Bv.w, Cv.x,Cv.y,Cv.z,Cv.w};
                ull rd[11];
                #pragma unroll
                for (int j = 0; j < 11; j++) rd[j] = pk2(r[j], r[j]);
                #pragma unroll
                for (int kx = 0; kx < 9; kx++) {
                    const ulonglong2* w = (const ulonglong2*)&s_w[(ky*9 + kx)*16];
                    ulonglong2 wA = w[0], wB = w[1], wC = w[2], wD = w[3];  // 4x LDS.128
                    ull wv0 = wA.x, wv1 = wA.y, wv2 = wB.x, wv3 = wB.y;
                    ull wv4 = wC.x, wv5 = wC.y, wv6 = wD.x, wv7 = wD.y;
                    ull i0 = rd[kx], i1 = rd[kx+2];
                    acc[0][0] = fma2(wv0, i0, acc[0][0]);
                    acc[0][1] = fma2(wv0, i1, acc[0][1]);
                    acc[1][0] = fma2(wv1, i0, acc[1][0]);
                    acc[1][1] = fma2(wv1, i1, acc[1][1]);
                    acc[2][0] = fma2(wv2, i0, acc[2][0]);
                    acc[2][1] = fma2(wv2, i1, acc[2][1]);
                    acc[3][0] = fma2(wv3, i0, acc[3][0]);
                    acc[3][1] = fma2(wv3, i1, acc[3][1]);
                    acc[4][0] = fma2(wv4, i0, acc[4][0]);
                    acc[4][1] = fma2(wv4, i1, acc[4][1]);
                    acc[5][0] = fma2(wv5, i0, acc[5][0]);
                    acc[5][1] = fma2(wv5, i1, acc[5][1]);
                    acc[6][0] = fma2(wv6, i0, acc[6][0]);
                    acc[6][1] = fma2(wv6, i1, acc[6][1]);
                    acc[7][0] = fma2(wv7, i0, acc[7][0]);
                    acc[7][1] = fma2(wv7, i1, acc[7][1]);
                }
            }
        }
    }
    if (active) {
        float* base = g_upart[ich];
        int ox0 = 2*oxp;
        #pragma unroll
        for (int s = 0; s < 2; s++) {
            int ox = ox0 + s;
            if (ox < 17) {
                int pos = oy*17 + ox;
                #pragma unroll
                for (int p = 0; p < 8; p++) {
                    float lo, hi; upk2(acc[p][s], lo, hi);
                    int oc0 = ocg*16 + p*2;
                    float b0 = (ich == 0) ? prim_b[oc0]   : 0.f;
                    float b1 = (ich == 0) ? prim_b[oc0+1] : 0.f;
                    base[(size_t)(b*64 + oc0  )*289 + pos] = lo + b0;
                    base[(size_t)(b*64 + oc0+1)*289 + pos] = hi + b1;
                }
            }
        }
    }
}

// ---------------- squash over routes: per (b,i) scale (sums the 4 partials) -------
__global__ void __launch_bounds__(256) k_sqnorm() {
    __shared__ float red[256];
    int bi = blockIdx.x;                     // b*8 + i
    const float* p0 = g_upart[0] + bi*2312;
    const float* p1 = g_upart[1] + bi*2312;
    const float* p2 = g_upart[2] + bi*2312;
    const float* p3 = g_upart[3] + bi*2312;
    float s = 0.f;
    for (int k = threadIdx.x; k < 2312; k += 256) {
        float v = ((p0[k] + p1[k]) + p2[k]) + p3[k];
        s += v*v;
    }
    red[threadIdx.x] = s; __syncthreads();
    for (int st = 128; st; st >>= 1) {
        if (threadIdx.x < st) red[threadIdx.x] += red[threadIdx.x + st];
        __syncthreads();
    }
    if (threadIdx.x == 0) {
        float sn = red[0];
        g_scale[bi] = sn / ((1.f + sn) * sqrtf(fmaxf(sn, 1e-30f)));
    }
}

// ---------------- x2 transpose (sums the 4 partials; coalesced both sides) --------
__global__ void __launch_bounds__(256) k_xpose() {
    __shared__ float tile[32][33];
    int ch = blockIdx.x;                 // 0..63
    int st = blockIdx.y;                 // s tile 0..9
    int bt = blockIdx.z;                 // b tile 0..3
    int tx = threadIdx.x & 31, ty = threadIdx.x >> 5;
    int i = ch >> 3, rr = ch & 7;
    int s0 = st*32, b0 = bt*32;
    #pragma unroll
    for (int bb = ty; bb < 32; bb += 8) {
        int s = s0 + tx;
        float v = 0.f;
        if (s < 289) {
            int b = b0 + bb;
            size_t idx = (size_t)(b*64 + ch)*289 + s;
            v = g_scale[b*8 + i] *
                (((g_upart[0][idx] + g_upart[1][idx]) + g_upart[2][idx]) + g_upart[3][idx]);
        }
        tile[bb][tx] = v;
    }
    __syncthreads();
    #pragma unroll
    for (int ss = ty; ss < 32; ss += 8) {
        int s = s0 + ss;
        if (s < 289) {
            int r = rr*289 + s;
            g_x2[(size_t)r*1024 + i*128 + b0 + tx] = tile[tx][ss];
        }
    }
}

// ---------------- routing (u_hat never materialized; softmax fused) -------------
__global__ void __launch_bounds__(128) k_spass2(const float* __restrict__ W_digit) {
    __shared__ float s_c[34];
    __shared__ __align__(16) float s_w[34*128];     // [rl][i*16+o], c-scaled
    int sl = blockIdx.x, c = blockIdx.y, t = threadIdx.x;
    int r0 = sl*34;
    if (t < 34) {                                    // inline softmax of b_ij row
        const float* bp = g_bij + (r0 + t)*10;
        float v[10], m = -1e30f;
        #pragma unroll
        for (int j = 0; j < 10; j++) { v[j] = bp[j]; m = fmaxf(m, v[j]); }
        float s = 0.f;
        #pragma unroll
        for (int j = 0; j < 10; j++) s += expf(v[j] - m);
        s_c[t] = expf(v[c] - m) / s;
    }
    __syncthreads();
    for (int e = t; e < 34*128; e += 128) {
        int rl = e >> 7, rem = e & 127;             // rem = o*8+i
        int o = rem >> 3, i = rem & 7;
        s_w[rl*128 + i*16 + o] = s_c[rl] * W_digit[(size_t)(r0+rl)*1280 + c*128 + rem];
    }
    __syncthreads();
    ull acc[8];
    #pragma unroll
    for (int p = 0; p < 8; p++) acc[p] = pk2(0.f, 0.f);
    int b = t;
    for (int rl = 0; rl < 34; rl++) {
        int r = r0 + rl;
        float xv[8];
        #pragma unroll
        for (int i = 0; i < 8; i++) xv[i] = g_x2[(r*8+i)*128 + b];
        const ull* wrow = (const ull*)&s_w[rl*128];
        #pragma unroll
        for (int i = 0; i < 8; i++) {
            ull xi = pk2(xv[i], xv[i]);
            #pragma unroll
            for (int op = 0; op < 8; op++)
                acc[op] = fma2(wrow[i*8+op], xi, acc[op]);
        }
    }
    float* outp = g_spart2 + ((size_t)(sl*128 + b))*160 + c*16;
    #pragma unroll
    for (int op = 0; op < 8; op++) {
        float lo, hi; upk2(acc[op], lo, hi);
        outp[op*2] = lo; outp[op*2+1] = hi;
    }
}

// reduce 68 slices + squash over o; on the final iteration also runs the head MLP
__global__ void __launch_bounds__(160) k_reduce2(float* __restrict__ out, int write_out,
                                                 const float* __restrict__ w1,
                                                 const float* __restrict__ b1,
                                                 const float* __restrict__ w2,
                                                 const float* __restrict__ b2) {
    __shared__ float s_v[160];
    __shared__ float s_red[128];
    int b = blockIdx.x, t = threadIdx.x;            // t = c*16+o
    float s = 0.f;
    #pragma unroll 4
    for (int sl = 0; sl < 68; sl++)
        s += g_spart2[((size_t)(sl*128 + b))*160 + t];
    float sq = s*s;
    #pragma unroll
    for (int off = 8; off; off >>= 1) sq += __shfl_xor_sync(0xffffffffu, sq, off, 16);
    float scale = sq / ((1.f + sq) * sqrtf(fmaxf(sq, 1e-30f)));
    float v = s * scale;
    g_v[b*160 + t] = v;
    if (!write_out) return;
    // ---- final iteration: emit v and run head MLP for this b ----
    out[b*160 + t] = v;
    s_v[t] = v;
    __syncthreads();
    for (int c = 0; c < 10; c++) {
        float hv = 0.f;
        if (t < 100) {
            float a = b1[c*100 + t];
            #pragma unroll
            for (int i = 0; i < 16; i++) a += s_v[c*16 + i] * w1[(c*16 + i)*100 + t];
            hv = tanhf(a) * w2[c*100 + t];
        }
        if (t < 128) s_red[t] = hv;
        __syncthreads();
        for (int st = 64; st; st >>= 1) {
            if (t < st) s_red[t] += s_red[t + st];
            __syncthreads();
        }
        if (t == 0) {
            float logit = s_red[0] + b2[c];
            out[20480 + c*128 + b] = 1.f / (1.f + expf(-logit));
        }
        __syncthreads();
    }
}

// a[r,c] = (1/128) sum_{o,i} W[r,c,o,i] * (sum_b x2[r,i,b] v[b,c,o]); b_ij += a
__global__ void __launch_bounds__(160) k_apass2(const float* __restrict__ W_digit) {
    extern __shared__ float sm[];
    float* s_v = sm;             // 20480 floats (80 KB)
    float* s_x = sm + 20480;     // 8192 floats  (32 KB), layout [rr][b][i]
    int t = threadIdx.x;
    int r0 = blockIdx.x * 8;
    for (int idx = t; idx < 20480; idx += 160) s_v[idx] = g_v[idx];
    for (int d = t; d < 8192; d += 160) {
        int rr = d >> 10, rem = d & 1023, b = rem >> 3, i = rem & 7;
        s_x[d] = g_x2[(size_t)(r0+rr)*1024 + i*128 + b];
    }
    __syncthreads();
    for (int rr = 0; rr < 8; rr++) {
        int r = r0 + rr;
        ull accp[4];
        #pragma unroll
        for (int p = 0; p < 4; p++) accp[p] = pk2(0.f, 0.f);
        #pragma unroll 4
        for (int b = 0; b < 128; b++) {
            float vb = s_v[b*160 + t];
            ull vv = pk2(vb, vb);
            const ull* xp = (const ull*)&s_x[rr*1024 + b*8];
            #pragma unroll
            for (int ip = 0; ip < 4; ip++)
                accp[ip] = fma2(xp[ip], vv, accp[ip]);
        }
        float G[8];
        #pragma unroll
        for (int ip = 0; ip < 4; ip++) upk2(accp[ip], G[2*ip], G[2*ip+1]);
        const float4* wp = (const float4*)(W_digit + (size_t)r*1280 + t*8);
        float4 wa = wp[0], wb4 = wp[1];
        float partial = wa.x*G[0] + wa.y*G[1] + wa.z*G[2] + wa.w*G[3]
                      + wb4.x*G[4] + wb4.y*G[5] + wb4.z*G[6] + wb4.w*G[7];
        #pragma unroll
        for (int off = 8; off; off >>= 1) partial += __shfl_xor_sync(0xffffffffu, partial, off, 16);
        if ((t & 15) == 0) g_bij[r*10 + (t >> 4)] += partial * (1.f/128.f);
    }
}

// ---------------- launch (conv2 at 0-based index 3: the profiled slot) ----------------
extern "C" void kernel_launch(void* const* d_in, const int* in_sizes, int n_in,
                              void* d_out, int out_size) {
    const float* data    = (const float*)d_in[0];
    const float* conv_w  = (const float*)d_in[1];
    const float* conv_b  = (const float*)d_in[2];
    const float* prim_w  = (const float*)d_in[3];
    const float* prim_b  = (const float*)d_in[4];
    const float* W_digit = (const float*)d_in[5];
    const float* head_w1 = (const float*)d_in[6];
    const float* head_b1 = (const float*)d_in[7];
    const float* head_w2 = (const float*)d_in[8];
    const float* head_b2 = (const float*)d_in[9];
    float* out = (float*)d_out;

    cudaFuncSetAttribute(k_apass2, cudaFuncAttributeMaxDynamicSharedMemorySize, 114688);

    k_prep<<<91, 256>>>(conv_w);                          // 0 (init + pack_w1)
    k_pack_w2<<<(165888 + 255)/256, 256>>>(prim_w);       // 1
    k_conv1<<<dim3(8, 128), 256>>>(data, conv_b);         // 2
    k_conv2<<<dim3(16, 128), 160>>>(prim_b);              // 3  <- profiled slot
    k_sqnorm<<<1024, 256>>>();                             // 4
    k_xpose<<<dim3(64, 10, 4), 256>>>();                   // 5
    for (int it = 0; it < 3; it++) {
        k_spass2<<<dim3(68, 10), 128>>>(W_digit);
        k_reduce2<<<128, 160>>>(out, it == 2 ? 1 : 0,
                                head_w1, head_b1, head_w2, head_b2);
        if (it < 2) k_apass2<<<289, 160, 114688>>>(W_digit);
    }
}